// round 14
// baseline (speedup 1.0000x reference)
#include <cuda_runtime.h>
#include <cuda_bf16.h>
#include <cstdint>
#include <math.h>

// ---------------------------------------------------------------------------
// GPT2 attention block — tf32 mma.sync.
//   prepass: round x, round+transpose weights
//   x @ W_attn + b_attn -> qkv (rounded) + V^T  [gemm_tc: 3-stage, 1 barrier]
//   flash attention BQ=128, BKV=64, Q in regs, ldmatrix K/P/V^T,
//     P stored into the consumed K smem slot -> 64KB smem, 3 blocks/SM
//   att @ W_proj + b_proj -> out                [gemm_tc]
// ---------------------------------------------------------------------------

#define TT      4096
#define CC      1024
#define NHEAD   16
#define HDIM    64
#define SCALE   0.125f

__device__ float g_qkv[TT * 3 * CC];
__device__ float g_att[TT * CC];
__device__ float g_xr [TT * CC];
__device__ float g_wat[3 * CC * CC];
__device__ float g_wpt[CC * CC];
__device__ float g_vt [CC * TT];        // V^T: [h*64+d][t], rounded

// ============================ helpers ======================================
__device__ __forceinline__ uint32_t smem_u32(const void* p) {
    uint32_t a;
    asm("{ .reg .u64 t; cvta.to.shared.u64 t, %1; cvt.u32.u64 %0, t; }"
        : "=r"(a) : "l"(p));
    return a;
}
__device__ __forceinline__ unsigned cvt_tf32(float x) {
    unsigned u;
    asm("cvt.rna.tf32.f32 %0, %1;" : "=r"(u) : "f"(x));
    return u;
}
__device__ __forceinline__ float tf32r(float x) {
    return __uint_as_float(cvt_tf32(x));
}
__device__ __forceinline__ void mma_tf32(float* d, const unsigned* a,
                                         unsigned b0, unsigned b1) {
    asm volatile(
        "mma.sync.aligned.m16n8k8.row.col.f32.tf32.tf32.f32 "
        "{%0,%1,%2,%3}, {%4,%5,%6,%7}, {%8,%9}, {%0,%1,%2,%3};"
        : "+f"(d[0]), "+f"(d[1]), "+f"(d[2]), "+f"(d[3])
        : "r"(a[0]), "r"(a[1]), "r"(a[2]), "r"(a[3]), "r"(b0), "r"(b1));
}
__device__ __forceinline__ void ldsm4(unsigned* r, uint32_t addr) {
    asm volatile("ldmatrix.sync.aligned.m8n8.x4.shared.b16 {%0,%1,%2,%3}, [%4];"
                 : "=r"(r[0]), "=r"(r[1]), "=r"(r[2]), "=r"(r[3]) : "r"(addr));
}
__device__ __forceinline__ void cpa16(uint32_t dst, const float* src) {
    asm volatile("cp.async.cg.shared.global [%0], [%1], 16;" :: "r"(dst), "l"(src));
}
#define CP_COMMIT() asm volatile("cp.async.commit_group;" ::: "memory")
#define CP_WAIT0()  asm volatile("cp.async.wait_group 0;" ::: "memory")
#define CP_WAIT1()  asm volatile("cp.async.wait_group 1;" ::: "memory")

// ============================ pre-pass kernels =============================
__global__ void round_copy(const float* __restrict__ in, float* __restrict__ out, int n4) {
    int i = blockIdx.x * blockDim.x + threadIdx.x;
    if (i < n4) {
        float4 v = ((const float4*)in)[i];
        v.x = tf32r(v.x); v.y = tf32r(v.y); v.z = tf32r(v.z); v.w = tf32r(v.w);
        ((float4*)out)[i] = v;
    }
}
__global__ void transpose_round(const float* __restrict__ W, float* __restrict__ Wt,
                                int K, int N) {
    __shared__ float t[32][33];
    int n0 = blockIdx.x * 32, k0 = blockIdx.y * 32;
    int tx = threadIdx.x, ty = threadIdx.y;
    #pragma unroll
    for (int j = 0; j < 32; j += 8)
        t[ty + j][tx] = W[(size_t)(k0 + ty + j) * N + n0 + tx];
    __syncthreads();
    #pragma unroll
    for (int j = 0; j < 32; j += 8)
        Wt[(size_t)(n0 + ty + j) * K + k0 + tx] = tf32r(t[tx][ty + j]);
}

// ============================ GEMM =========================================
// C[M,N] = A[M,K] @ Bt[N,K]^T + bias. Block 128x128, 8 warps (2x4),
// warp tile 64x32. 3-stage cp.async pipeline, ONE barrier per k-tile.
// If Vt != nullptr and bn >= 2048, also write transposed output to Vt.
#define GEMM_SMEM (3 * 32768)

__global__ __launch_bounds__(256, 2)
void gemm_tc(const float* __restrict__ A, const float* __restrict__ Bt,
             const float* __restrict__ bias, float* __restrict__ C,
             int M, int N, int K, int round_out, float* __restrict__ Vt)
{
    extern __shared__ char dsm[];
    const uint32_t sb = smem_u32(dsm);

    const int tid  = threadIdx.x;
    const int lane = tid & 31;
    const int qrl  = lane >> 2;
    const int quad = lane & 3;
    const int w    = tid >> 5;
    const int wm   = w >> 2;
    const int wn   = w & 3;
    const int bm   = blockIdx.y * 128;
    const int bn   = blockIdx.x * 128;

    float d[4][4][4];
    #pragma unroll
    for (int im = 0; im < 4; im++)
        #pragma unroll
        for (int jn = 0; jn < 4; jn++)
            #pragma unroll
            for (int r = 0; r < 4; r++) d[im][jn][r] = 0.0f;

    const int r  = tid >> 1;
    const int c0 = (tid & 1) * 4;
    const float* gA = A  + (size_t)(bm + r) * K;
    const float* gB = Bt + (size_t)(bn + r) * K;
    const uint32_t rowoff = (uint32_t)r * 128u;
    const int rx = r & 7;

    const int NST = K / 32;

    // prologue: stages 0 and 1
    #pragma unroll
    for (int st = 0; st < 2; st++) {
        const uint32_t slot = (uint32_t)st * 32768u;
        #pragma unroll
        for (int i = 0; i < 4; i++) {
            int c = c0 + i;
            uint32_t doff = slot + rowoff + (uint32_t)((c ^ rx) << 4);
            cpa16(sb + doff,          gA + st * 32 + c * 4);
            cpa16(sb + 16384 + doff,  gB + st * 32 + c * 4);
        }
        CP_COMMIT();
    }

    const int mtx = lane >> 3;
    const int rr  = lane & 7;

    for (int s = 0; s < NST; s++) {
        CP_WAIT1();            // stage s complete (pending {s, s+1})
        __syncthreads();       // all threads done with stage s-1 compute

        if (s + 2 < NST) {     // issue s+2 into the slot consumed at s-1
            const uint32_t slot = (uint32_t)((s + 2) % 3) * 32768u;
            const int k0 = (s + 2) * 32;
            #pragma unroll
            for (int i = 0; i < 4; i++) {
                int c = c0 + i;
                uint32_t doff = slot + rowoff + (uint32_t)((c ^ rx) << 4);
                cpa16(sb + doff,         gA + k0 + c * 4);
                cpa16(sb + 16384 + doff, gB + k0 + c * 4);
            }
        }
        CP_COMMIT();

        const uint32_t Ab = sb + (uint32_t)(s % 3) * 32768u;
        const uint32_t Bb = Ab + 16384u;

        #pragma unroll
        for (int ks = 0; ks < 4; ks++) {
            unsigned a[4][4];
            #pragma unroll
            for (int im = 0; im < 4; im++) {
                int m_row = wm * 64 + im * 16 + rr + ((mtx & 1) << 3);
                int kch   = ks * 2 + (mtx >> 1);
                uint32_t addr = Ab + (uint32_t)m_row * 128u
                              + (uint32_t)((kch ^ (m_row & 7)) << 4);
                ldsm4(a[im], addr);
            }
            unsigned b[2][4];
            #pragma unroll
            for (int j2 = 0; j2 < 2; j2++) {
                int n_row = wn * 32 + j2 * 16 + rr + ((mtx >> 1) << 3);
                int kch   = ks * 2 + (mtx & 1);
                uint32_t addr = Bb + (uint32_t)n_row * 128u
                              + (uint32_t)((kch ^ (n_row & 7)) << 4);
                ldsm4(b[j2], addr);
            }
            #pragma unroll
            for (int im = 0; im < 4; im++)
                #pragma unroll
                for (int jn = 0; jn < 4; jn++)
                    mma_tf32(d[im][jn], a[im],
                             b[jn >> 1][(jn & 1) * 2],
                             b[jn >> 1][(jn & 1) * 2 + 1]);
        }
    }

    const bool do_vt = (Vt != nullptr) && (bn >= 2048);

    #pragma unroll
    for (int im = 0; im < 4; im++) {
        int r_lo = bm + wm * 64 + im * 16 + qrl;
        #pragma unroll
        for (int jn = 0; jn < 4; jn++) {
            int col = bn + wn * 32 + jn * 8 + 2 * quad;
            float b0 = bias[col], b1 = bias[col + 1];
            float2 v0, v1;
            if (round_out) {
                v0 = make_float2(tf32r(d[im][jn][0] + b0), tf32r(d[im][jn][1] + b1));
                v1 = make_float2(tf32r(d[im][jn][2] + b0), tf32r(d[im][jn][3] + b1));
            } else {
                v0 = make_float2(d[im][jn][0] + b0, d[im][jn][1] + b1);
                v1 = make_float2(d[im][jn][2] + b0, d[im][jn][3] + b1);
            }
            *(float2*)&C[(size_t)r_lo * N + col]       = v0;
            *(float2*)&C[(size_t)(r_lo + 8) * N + col] = v1;
            if (do_vt) {
                int vc = col - 2048;
                Vt[(size_t)vc * M + r_lo]           = v0.x;
                Vt[(size_t)vc * M + r_lo + 8]       = v1.x;
                Vt[(size_t)(vc + 1) * M + r_lo]     = v0.y;
                Vt[(size_t)(vc + 1) * M + r_lo + 8] = v1.y;
            }
        }
    }
}

// ============================ flash attention ==============================
// BQ=128, 4 warps x 32 q rows (2 m-tiles), BKV=64.
// Q in registers (pre-scaled). K from g_qkv, V^T from g_vt, double-buffered.
// After S-phase, P is stored INTO the consumed K slot (swizzled 128B rows)
// and read back via ldmatrix. smem = 64KB -> 3 blocks/SM.
#define ATT_SMEM 65536

__device__ __forceinline__ void att_stage(uint32_t sb, int tid, int h, int kt) {
    const uint32_t kslot = sb + (uint32_t)(kt & 1) * 16384u;
    const uint32_t vslot = sb + 32768u + (uint32_t)(kt & 1) * 16384u;
    const int k0 = kt * 64;
    #pragma unroll
    for (int i = 0; i < 8; i++) {
        int idx = tid + i * 128;
        int r = idx >> 4, c = idx & 15;
        uint32_t doff = (uint32_t)r * 256u + (uint32_t)((c ^ (r & 7)) << 4);
        // K rows: 64 keys x 64 d
        cpa16(kslot + doff,
              &g_qkv[(size_t)(k0 + r) * (3 * CC) + CC + h * HDIM + c * 4]);
        // V^T rows: 64 d x 64 keys
        cpa16(vslot + doff,
              &g_vt[(size_t)(h * HDIM + r) * TT + k0 + c * 4]);
    }
}

__global__ __launch_bounds__(128, 3)
void flash_attn_tc()
{
    extern __shared__ char asmem[];
    const uint32_t sb = smem_u32(asmem);

    const int h    = blockIdx.y;
    const int qt   = 31 - (int)blockIdx.x;   // heavy first
    const int q0   = qt * 128;
    const int tid  = threadIdx.x;
    const int lane = tid & 31;
    const int w    = tid >> 5;               // 0..3
    const int qrl  = lane >> 2;
    const int quad = lane & 3;
    const int mtx  = lane >> 3;
    const int rr   = lane & 7;

    // ---- Q fragments in registers, pre-scaled by SCALE (exact) ----
    unsigned qa[2][8][4];
    #pragma unroll
    for (int im = 0; im < 2; im++) {
        int row = q0 + w * 32 + im * 16 + qrl;
        const float* p0 = &g_qkv[(size_t)row * (3 * CC) + h * HDIM + quad];
        const float* p1 = p0 + (size_t)8 * (3 * CC);
        #pragma unroll
        for (int ks = 0; ks < 8; ks++) {
            qa[im][ks][0] = __float_as_uint(p0[ks * 8]     * SCALE);
            qa[im][ks][1] = __float_as_uint(p1[ks * 8]     * SCALE);
            qa[im][ks][2] = __float_as_uint(p0[ks * 8 + 4] * SCALE);
            qa[im][ks][3] = __float_as_uint(p1[ks * 8 + 4] * SCALE);
        }
    }

    float o[2][8][4];
    #pragma unroll
    for (int im = 0; im < 2; im++)
        #pragma unroll
        for (int n = 0; n < 8; n++)
            #pragma unroll
            for (int r = 0; r < 4; r++) o[im][n][r] = 0.0f;
    float mm[2][2] = {{-1e30f, -1e30f}, {-1e30f, -1e30f}};
    float ll[2][2] = {{0.0f, 0.0f}, {0.0f, 0.0f}};

    const int n_tiles = 2 * (qt + 1);

    att_stage(sb, tid, h, 0);
    CP_COMMIT();

    for (int kt = 0; kt < n_tiles; kt++) {
        CP_WAIT0();            // stage kt complete
        __syncthreads();       // all warps done with stage kt-1 compute (incl. P)

        if (kt + 1 < n_tiles) att_stage(sb, tid, h, kt + 1);
        CP_COMMIT();

        const uint32_t Ksb = sb + (uint32_t)(kt & 1) * 16384u;
        const uint32_t Vtb = sb + 32768u + (uint32_t)(kt & 1) * 16384u;
        char* Pbase = asmem + (kt & 1) * 16384;
        const int k0 = kt * 64;
        const bool active = (k0 < q0 + w * 32 + 32);

        float s[2][8][4];
        float mn[2][2], al[2][2];

        if (active) {
            // ---- S = (Q*SCALE) K^T ----
            #pragma unroll
            for (int im = 0; im < 2; im++)
                #pragma unroll
                for (int j = 0; j < 8; j++)
                    #pragma unroll
                    for (int r = 0; r < 4; r++) s[im][j][r] = 0.0f;

            #pragma unroll
            for (int ks = 0; ks < 8; ks++) {
                unsigned kb[4][4];
                #pragma unroll
                for (int j2 = 0; j2 < 4; j2++) {
                    int n_row = j2 * 16 + rr + ((mtx >> 1) << 3);
                    int kch   = ks * 2 + (mtx & 1);
                    uint32_t addr = Ksb + (uint32_t)n_row * 256u
                                  + (uint32_t)((kch ^ (n_row & 7)) << 4);
                    ldsm4(kb[j2], addr);
                }
                #pragma unroll
                for (int j = 0; j < 8; j++) {
                    unsigned b0 = kb[j >> 1][(j & 1) * 2];
                    unsigned b1 = kb[j >> 1][(j & 1) * 2 + 1];
                    mma_tf32(s[0][j], qa[0][ks], b0, b1);
                    mma_tf32(s[1][j], qa[1][ks], b0, b1);
                }
            }

            // ---- mask + full-tile row max + rescale O ----
            #pragma unroll
            for (int im = 0; im < 2; im++) {
                const int base   = q0 + w * 32 + im * 16;
                const int row_lo = base + qrl;
                const bool domask = (k0 + 63 > base);
                float tml = -1e30f, tmh = -1e30f;
                #pragma unroll
                for (int j = 0; j < 8; j++) {
                    if (domask) {
                        int col = k0 + j * 8 + 2 * quad;
                        if (col     > row_lo)     s[im][j][0] = -1e30f;
                        if (col + 1 > row_lo)     s[im][j][1] = -1e30f;
                        if (col     > row_lo + 8) s[im][j][2] = -1e30f;
                        if (col + 1 > row_lo + 8) s[im][j][3] = -1e30f;
                    }
                    tml = fmaxf(tml, fmaxf(s[im][j][0], s[im][j][1]));
                    tmh = fmaxf(tmh, fmaxf(s[im][j][2], s[im][j][3]));
                }
                tml = fmaxf(tml, __shfl_xor_sync(0xffffffffu, tml, 1));
                tml = fmaxf(tml, __shfl_xor_sync(0xffffffffu, tml, 2));
                tmh = fmaxf(tmh, __shfl_xor_sync(0xffffffffu, tmh, 1));
                tmh = fmaxf(tmh, __shfl_xor_sync(0xffffffffu, tmh, 2));

                mn[im][0] = fmaxf(mm[im][0], tml);
                mn[im][1] = fmaxf(mm[im][1], tmh);
                al[im][0] = __expf(mm[im][0] - mn[im][0]);
                al[im][1] = __expf(mm[im][1] - mn[im][1]);
                mm[im][0] = mn[im][0]; mm[im][1] = mn[im][1];
                #pragma unroll
                for (int n = 0; n < 8; n++) {
                    o[im][n][0] *= al[im][0]; o[im][n][1] *= al[im][0];
                    o[im][n][2] *= al[im][1]; o[im][n][3] *= al[im][1];
                }
            }
        }

        // all warps must finish reading the K slot before P overwrites it
        __syncthreads();

        if (active) {
            // ---- two 32-key halves: exp + store P into K slot, then PV ----
            float rs[2][2] = {{0.0f, 0.0f}, {0.0f, 0.0f}};
            #pragma unroll
            for (int hf = 0; hf < 2; hf++) {
                #pragma unroll
                for (int im = 0; im < 2; im++) {
                    const int rl = w * 32 + im * 16 + qrl;
                    #pragma unroll
                    for (int jj = 0; jj < 4; jj++) {
                        int j = hf * 4 + jj;
                        float p0 = __expf(s[im][j][0] - mn[im][0]);
                        float p1 = __expf(s[im][j][1] - mn[im][0]);
                        float p2 = __expf(s[im][j][2] - mn[im][1]);
                        float p3 = __expf(s[im][j][3] - mn[im][1]);
                        rs[im][0] += p0 + p1;
                        rs[im][1] += p2 + p3;
                        // swizzled 128B-row store: chunk c = 2*jj + (quad>>1)
                        int c = 2 * jj + (quad >> 1);
                        uint32_t sub = (uint32_t)((quad & 1) * 8);
                        *(float2*)(Pbase + rl * 128
                                   + ((c ^ (rl & 7)) << 4) + sub) =
                            make_float2(tf32r(p0), tf32r(p1));
                        int rl8 = rl + 8;
                        *(float2*)(Pbase + rl8 * 128
                                   + ((c ^ (rl8 & 7)) << 4) + sub) =
                            make_float2(tf32r(p2), tf32r(p3));
                    }
                }
                __syncwarp();

                #pragma unroll
                for (int ksl = 0; ksl < 4; ksl++) {
                    // P a-fragments via ldmatrix (GEMM-A formula, 128B rows)
                    unsigned ap[2][4];
                    #pragma unroll
                    for (int im = 0; im < 2; im++) {
                        int prow = w * 32 + im * 16 + rr + ((mtx & 1) << 3);
                        int kch  = ksl * 2 + (mtx >> 1);
                        uint32_t addr = Ksb + (uint32_t)prow * 128u
                                      + (uint32_t)((kch ^ (prow & 7)) << 4);
                        ldsm4(ap[im], addr);
                    }
                    // V^T b-fragments via ldmatrix (GEMM-B formula)
                    unsigned vb[4][4];
                    #pragma unroll
                    for (int j2 = 0; j2 < 4; j2++) {
                        int vrow = j2 * 16 + rr + ((mtx >> 1) << 3);
                        int kch  = (hf * 4 + ksl) * 2 + (mtx & 1);
                        uint32_t addr = Vtb + (uint32_t)vrow * 256u
                                      + (uint32_t)((kch ^ (vrow & 7)) << 4);
                        ldsm4(vb[j2], addr);
                    }
                    #pragma unroll
                    for (int im = 0; im < 2; im++)
                        #pragma unroll
                        for (int n = 0; n < 8; n++)
                            mma_tf32(o[im][n], ap[im],
                                     vb[n >> 1][(n & 1) * 2],
                                     vb[n >> 1][(n & 1) * 2 + 1]);
                }
                __syncwarp();
            }

            // ---- l update ----
            #pragma unroll
            for (int im = 0; im < 2; im++) {
                float rsl = rs[im][0], rsh = rs[im][1];
                rsl += __shfl_xor_sync(0xffffffffu, rsl, 1);
                rsl += __shfl_xor_sync(0xffffffffu, rsl, 2);
                rsh += __shfl_xor_sync(0xffffffffu, rsh, 1);
                rsh += __shfl_xor_sync(0xffffffffu, rsh, 2);
                ll[im][0] = ll[im][0] * al[im][0] + rsl;
                ll[im][1] = ll[im][1] * al[im][1] + rsh;
            }
        }
    }

    // ---- epilogue: normalize + round (feeds tf32 proj GEMM) ----
    #pragma unroll
    for (int im = 0; im < 2; im++) {
        float invl = 1.0f / ll[im][0];
        float invh = 1.0f / ll[im][1];
        int rl = q0 + w * 32 + im * 16 + qrl;
        #pragma unroll
        for (int n = 0; n < 8; n++) {
            int col = h * HDIM + n * 8 + 2 * quad;
            *(float2*)&g_att[(size_t)rl * CC + col] =
                make_float2(tf32r(o[im][n][0] * invl), tf32r(o[im][n][1] * invl));
            *(float2*)&g_att[(size_t)(rl + 8) * CC + col] =
                make_float2(tf32r(o[im][n][2] * invh), tf32r(o[im][n][3] * invh));
        }
    }
}

// ================================ launch ===================================
extern "C" void kernel_launch(void* const* d_in, const int* in_sizes, int n_in,
                              void* d_out, int out_size)
{
    const float* x      = (const float*)d_in[0];
    const float* W_attn = (const float*)d_in[1];
    const float* b_attn = (const float*)d_in[2];
    const float* W_proj = (const float*)d_in[3];
    const float* b_proj = (const float*)d_in[4];
    float*       out    = (float*)d_out;

    void *qkv_p, *att_p, *xr_p, *wat_p, *wpt_p, *vt_p;
    cudaGetSymbolAddress(&qkv_p, g_qkv);
    cudaGetSymbolAddress(&att_p, g_att);
    cudaGetSymbolAddress(&xr_p,  g_xr);
    cudaGetSymbolAddress(&wat_p, g_wat);
    cudaGetSymbolAddress(&wpt_p, g_wpt);
    cudaGetSymbolAddress(&vt_p,  g_vt);
    float* qkv = (float*)qkv_p;
    float* att = (float*)att_p;
    float* xr  = (float*)xr_p;
    float* wat = (float*)wat_p;
    float* wpt = (float*)wpt_p;
    float* vt  = (float*)vt_p;

    cudaFuncSetAttribute(gemm_tc,
                         cudaFuncAttributeMaxDynamicSharedMemorySize, GEMM_SMEM);
    cudaFuncSetAttribute(flash_attn_tc,
                         cudaFuncAttributeMaxDynamicSharedMemorySize, ATT_SMEM);

    // 0) pre-pass
    {
        int n4 = TT * CC / 4;
        round_copy<<<(n4 + 255) / 256, 256>>>(x, xr, n4);
        transpose_round<<<dim3(3 * CC / 32, CC / 32), dim3(32, 8)>>>(W_attn, wat, CC, 3 * CC);
        transpose_round<<<dim3(CC / 32, CC / 32), dim3(32, 8)>>>(W_proj, wpt, CC, CC);
    }
    // 1) QKV projection (rounded output + V^T side-write)
    {
        dim3 grid(3 * CC / 128, TT / 128);
        gemm_tc<<<grid, 256, GEMM_SMEM>>>(xr, wat, b_attn, qkv, TT, 3 * CC, CC, 1, vt);
    }
    // 2) Causal flash attention
    {
        dim3 grid(TT / 128, NHEAD);
        flash_attn_tc<<<grid, 128, ATT_SMEM>>>();
    }
    // 3) Output projection
    {
        dim3 grid(CC / 128, TT / 128);
        gemm_tc<<<grid, 256, GEMM_SMEM>>>(att, wpt, b_proj, out, TT, CC, CC, 0, nullptr);
    }
}

// round 15
// speedup vs baseline: 1.6651x; 1.6651x over previous
#include <cuda_runtime.h>
#include <cuda_bf16.h>
#include <cstdint>
#include <math.h>

// ---------------------------------------------------------------------------
// GPT2 attention block — tf32 mma.sync.
//   prepass: round x, round+transpose weights
//   x @ W_attn + b_attn -> qkv (rounded) + V^T  [gemm_tc: 3-stage, 1 barrier]
//   flash attention BQ=128, BKV=64, Q in regs, ldmatrix K/P/V^T,
//     1D grid with global heavy-first ordering -> att
//   att @ W_proj + b_proj -> out                [gemm_tc]
// ---------------------------------------------------------------------------

#define TT      4096
#define CC      1024
#define NHEAD   16
#define HDIM    64
#define SCALE   0.125f

__device__ float g_qkv[TT * 3 * CC];
__device__ float g_att[TT * CC];
__device__ float g_xr [TT * CC];
__device__ float g_wat[3 * CC * CC];
__device__ float g_wpt[CC * CC];
__device__ float g_vt [CC * TT];        // V^T: [h*64+d][t], rounded

// ============================ helpers ======================================
__device__ __forceinline__ uint32_t smem_u32(const void* p) {
    uint32_t a;
    asm("{ .reg .u64 t; cvta.to.shared.u64 t, %1; cvt.u32.u64 %0, t; }"
        : "=r"(a) : "l"(p));
    return a;
}
__device__ __forceinline__ unsigned cvt_tf32(float x) {
    unsigned u;
    asm("cvt.rna.tf32.f32 %0, %1;" : "=r"(u) : "f"(x));
    return u;
}
__device__ __forceinline__ float tf32r(float x) {
    return __uint_as_float(cvt_tf32(x));
}
__device__ __forceinline__ void mma_tf32(float* d, const unsigned* a,
                                         unsigned b0, unsigned b1) {
    asm volatile(
        "mma.sync.aligned.m16n8k8.row.col.f32.tf32.tf32.f32 "
        "{%0,%1,%2,%3}, {%4,%5,%6,%7}, {%8,%9}, {%0,%1,%2,%3};"
        : "+f"(d[0]), "+f"(d[1]), "+f"(d[2]), "+f"(d[3])
        : "r"(a[0]), "r"(a[1]), "r"(a[2]), "r"(a[3]), "r"(b0), "r"(b1));
}
__device__ __forceinline__ void ldsm4(unsigned* r, uint32_t addr) {
    asm volatile("ldmatrix.sync.aligned.m8n8.x4.shared.b16 {%0,%1,%2,%3}, [%4];"
                 : "=r"(r[0]), "=r"(r[1]), "=r"(r[2]), "=r"(r[3]) : "r"(addr));
}
__device__ __forceinline__ void cpa16(uint32_t dst, const float* src) {
    asm volatile("cp.async.cg.shared.global [%0], [%1], 16;" :: "r"(dst), "l"(src));
}
#define CP_COMMIT() asm volatile("cp.async.commit_group;" ::: "memory")
#define CP_WAIT0()  asm volatile("cp.async.wait_group 0;" ::: "memory")
#define CP_WAIT1()  asm volatile("cp.async.wait_group 1;" ::: "memory")

// ============================ pre-pass kernels =============================
__global__ void round_copy(const float* __restrict__ in, float* __restrict__ out, int n4) {
    int i = blockIdx.x * blockDim.x + threadIdx.x;
    if (i < n4) {
        float4 v = ((const float4*)in)[i];
        v.x = tf32r(v.x); v.y = tf32r(v.y); v.z = tf32r(v.z); v.w = tf32r(v.w);
        ((float4*)out)[i] = v;
    }
}
__global__ void transpose_round(const float* __restrict__ W, float* __restrict__ Wt,
                                int K, int N) {
    __shared__ float t[32][33];
    int n0 = blockIdx.x * 32, k0 = blockIdx.y * 32;
    int tx = threadIdx.x, ty = threadIdx.y;
    #pragma unroll
    for (int j = 0; j < 32; j += 8)
        t[ty + j][tx] = W[(size_t)(k0 + ty + j) * N + n0 + tx];
    __syncthreads();
    #pragma unroll
    for (int j = 0; j < 32; j += 8)
        Wt[(size_t)(n0 + ty + j) * K + k0 + tx] = tf32r(t[tx][ty + j]);
}

// ============================ GEMM =========================================
// C[M,N] = A[M,K] @ Bt[N,K]^T + bias. Block 128x128, 8 warps (2x4),
// warp tile 64x32. 3-stage cp.async pipeline, ONE barrier per k-tile.
// If Vt != nullptr and bn >= 2048, also write transposed output to Vt.
#define GEMM_SMEM (3 * 32768)

__global__ __launch_bounds__(256, 2)
void gemm_tc(const float* __restrict__ A, const float* __restrict__ Bt,
             const float* __restrict__ bias, float* __restrict__ C,
             int M, int N, int K, int round_out, float* __restrict__ Vt)
{
    extern __shared__ char dsm[];
    const uint32_t sb = smem_u32(dsm);

    const int tid  = threadIdx.x;
    const int lane = tid & 31;
    const int qrl  = lane >> 2;
    const int quad = lane & 3;
    const int w    = tid >> 5;
    const int wm   = w >> 2;
    const int wn   = w & 3;
    const int bm   = blockIdx.y * 128;
    const int bn   = blockIdx.x * 128;

    float d[4][4][4];
    #pragma unroll
    for (int im = 0; im < 4; im++)
        #pragma unroll
        for (int jn = 0; jn < 4; jn++)
            #pragma unroll
            for (int r = 0; r < 4; r++) d[im][jn][r] = 0.0f;

    const int r  = tid >> 1;
    const int c0 = (tid & 1) * 4;
    const float* gA = A  + (size_t)(bm + r) * K;
    const float* gB = Bt + (size_t)(bn + r) * K;
    const uint32_t rowoff = (uint32_t)r * 128u;
    const int rx = r & 7;

    const int NST = K / 32;

    // prologue: stages 0 and 1
    #pragma unroll
    for (int st = 0; st < 2; st++) {
        const uint32_t slot = (uint32_t)st * 32768u;
        #pragma unroll
        for (int i = 0; i < 4; i++) {
            int c = c0 + i;
            uint32_t doff = slot + rowoff + (uint32_t)((c ^ rx) << 4);
            cpa16(sb + doff,          gA + st * 32 + c * 4);
            cpa16(sb + 16384 + doff,  gB + st * 32 + c * 4);
        }
        CP_COMMIT();
    }

    const int mtx = lane >> 3;
    const int rr  = lane & 7;

    for (int s = 0; s < NST; s++) {
        CP_WAIT1();            // stage s complete (pending {s, s+1})
        __syncthreads();       // all threads done with stage s-1 compute

        if (s + 2 < NST) {     // issue s+2 into the slot consumed at s-1
            const uint32_t slot = (uint32_t)((s + 2) % 3) * 32768u;
            const int k0 = (s + 2) * 32;
            #pragma unroll
            for (int i = 0; i < 4; i++) {
                int c = c0 + i;
                uint32_t doff = slot + rowoff + (uint32_t)((c ^ rx) << 4);
                cpa16(sb + doff,         gA + k0 + c * 4);
                cpa16(sb + 16384 + doff, gB + k0 + c * 4);
            }
        }
        CP_COMMIT();

        const uint32_t Ab = sb + (uint32_t)(s % 3) * 32768u;
        const uint32_t Bb = Ab + 16384u;

        #pragma unroll
        for (int ks = 0; ks < 4; ks++) {
            unsigned a[4][4];
            #pragma unroll
            for (int im = 0; im < 4; im++) {
                int m_row = wm * 64 + im * 16 + rr + ((mtx & 1) << 3);
                int kch   = ks * 2 + (mtx >> 1);
                uint32_t addr = Ab + (uint32_t)m_row * 128u
                              + (uint32_t)((kch ^ (m_row & 7)) << 4);
                ldsm4(a[im], addr);
            }
            unsigned b[2][4];
            #pragma unroll
            for (int j2 = 0; j2 < 2; j2++) {
                int n_row = wn * 32 + j2 * 16 + rr + ((mtx >> 1) << 3);
                int kch   = ks * 2 + (mtx & 1);
                uint32_t addr = Bb + (uint32_t)n_row * 128u
                              + (uint32_t)((kch ^ (n_row & 7)) << 4);
                ldsm4(b[j2], addr);
            }
            #pragma unroll
            for (int im = 0; im < 4; im++)
                #pragma unroll
                for (int jn = 0; jn < 4; jn++)
                    mma_tf32(d[im][jn], a[im],
                             b[jn >> 1][(jn & 1) * 2],
                             b[jn >> 1][(jn & 1) * 2 + 1]);
        }
    }

    const bool do_vt = (Vt != nullptr) && (bn >= 2048);

    #pragma unroll
    for (int im = 0; im < 4; im++) {
        int r_lo = bm + wm * 64 + im * 16 + qrl;
        #pragma unroll
        for (int jn = 0; jn < 4; jn++) {
            int col = bn + wn * 32 + jn * 8 + 2 * quad;
            float b0 = bias[col], b1 = bias[col + 1];
            float2 v0, v1;
            if (round_out) {
                v0 = make_float2(tf32r(d[im][jn][0] + b0), tf32r(d[im][jn][1] + b1));
                v1 = make_float2(tf32r(d[im][jn][2] + b0), tf32r(d[im][jn][3] + b1));
            } else {
                v0 = make_float2(d[im][jn][0] + b0, d[im][jn][1] + b1);
                v1 = make_float2(d[im][jn][2] + b0, d[im][jn][3] + b1);
            }
            *(float2*)&C[(size_t)r_lo * N + col]       = v0;
            *(float2*)&C[(size_t)(r_lo + 8) * N + col] = v1;
            if (do_vt) {
                int vc = col - 2048;
                Vt[(size_t)vc * M + r_lo]           = v0.x;
                Vt[(size_t)vc * M + r_lo + 8]       = v1.x;
                Vt[(size_t)(vc + 1) * M + r_lo]     = v0.y;
                Vt[(size_t)(vc + 1) * M + r_lo + 8] = v1.y;
            }
        }
    }
}

// ============================ flash attention ==============================
// BQ=128, 4 warps x 32 q rows (2 m-tiles), BKV=64.
// Q in registers (pre-scaled). K from g_qkv, V^T from g_vt, cp.async
// double-buffered. S: ldmatrix K. PV: ldmatrix P (smem) + ldmatrix V^T.
// 1D grid, global heavy-first ordering: qt = 31 - b/16, h = b%16.
#define PSTR2 36
#define ATT_SMEM (65536 + 128 * PSTR2 * 4)

__device__ __forceinline__ void att_stage(uint32_t sb, int tid, int h, int kt) {
    const uint32_t kslot = sb + (uint32_t)(kt & 1) * 16384u;
    const uint32_t vslot = sb + 32768u + (uint32_t)(kt & 1) * 16384u;
    const int k0 = kt * 64;
    #pragma unroll
    for (int i = 0; i < 8; i++) {
        int idx = tid + i * 128;
        int r = idx >> 4, c = idx & 15;
        uint32_t doff = (uint32_t)r * 256u + (uint32_t)((c ^ (r & 7)) << 4);
        // K rows: 64 keys x 64 d
        cpa16(kslot + doff,
              &g_qkv[(size_t)(k0 + r) * (3 * CC) + CC + h * HDIM + c * 4]);
        // V^T rows: 64 d x 64 keys
        cpa16(vslot + doff,
              &g_vt[(size_t)(h * HDIM + r) * TT + k0 + c * 4]);
    }
}

__global__ __launch_bounds__(128)
void flash_attn_tc()
{
    extern __shared__ char asmem[];
    const uint32_t sb  = smem_u32(asmem);
    const uint32_t psb = sb + 65536u;
    float* Psm = (float*)(asmem + 65536);

    const int b    = (int)blockIdx.x;
    const int qt   = 31 - (b >> 4);          // global heavy-first
    const int h    = b & 15;
    const int q0   = qt * 128;
    const int tid  = threadIdx.x;
    const int lane = tid & 31;
    const int w    = tid >> 5;               // 0..3
    const int qrl  = lane >> 2;
    const int quad = lane & 3;
    const int mtx  = lane >> 3;
    const int rr   = lane & 7;

    // ---- Q fragments in registers, pre-scaled by SCALE (exact) ----
    unsigned qa[2][8][4];
    #pragma unroll
    for (int im = 0; im < 2; im++) {
        int row = q0 + w * 32 + im * 16 + qrl;
        const float* p0 = &g_qkv[(size_t)row * (3 * CC) + h * HDIM + quad];
        const float* p1 = p0 + (size_t)8 * (3 * CC);
        #pragma unroll
        for (int ks = 0; ks < 8; ks++) {
            qa[im][ks][0] = __float_as_uint(p0[ks * 8]     * SCALE);
            qa[im][ks][1] = __float_as_uint(p1[ks * 8]     * SCALE);
            qa[im][ks][2] = __float_as_uint(p0[ks * 8 + 4] * SCALE);
            qa[im][ks][3] = __float_as_uint(p1[ks * 8 + 4] * SCALE);
        }
    }

    float o[2][8][4];
    #pragma unroll
    for (int im = 0; im < 2; im++)
        #pragma unroll
        for (int n = 0; n < 8; n++)
            #pragma unroll
            for (int r = 0; r < 4; r++) o[im][n][r] = 0.0f;
    float mm[2][2] = {{-1e30f, -1e30f}, {-1e30f, -1e30f}};
    float ll[2][2] = {{0.0f, 0.0f}, {0.0f, 0.0f}};

    const int n_tiles = 2 * (qt + 1);

    att_stage(sb, tid, h, 0);
    CP_COMMIT();

    for (int kt = 0; kt < n_tiles; kt++) {
        CP_WAIT0();            // stage kt complete
        __syncthreads();       // all warps done with stage kt-1 compute

        if (kt + 1 < n_tiles) att_stage(sb, tid, h, kt + 1);
        CP_COMMIT();

        const uint32_t Ksb = sb + (uint32_t)(kt & 1) * 16384u;
        const uint32_t Vtb = sb + 32768u + (uint32_t)(kt & 1) * 16384u;
        const int k0 = kt * 64;
        const bool active = (k0 < q0 + w * 32 + 32);

        if (active) {
            // ---- S = (Q*SCALE) K^T ----
            float s[2][8][4];
            #pragma unroll
            for (int im = 0; im < 2; im++)
                #pragma unroll
                for (int j = 0; j < 8; j++)
                    #pragma unroll
                    for (int r = 0; r < 4; r++) s[im][j][r] = 0.0f;

            #pragma unroll
            for (int ks = 0; ks < 8; ks++) {
                unsigned kb[4][4];
                #pragma unroll
                for (int j2 = 0; j2 < 4; j2++) {
                    int n_row = j2 * 16 + rr + ((mtx >> 1) << 3);
                    int kch   = ks * 2 + (mtx & 1);
                    uint32_t addr = Ksb + (uint32_t)n_row * 256u
                                  + (uint32_t)((kch ^ (n_row & 7)) << 4);
                    ldsm4(kb[j2], addr);
                }
                #pragma unroll
                for (int j = 0; j < 8; j++) {
                    unsigned b0 = kb[j >> 1][(j & 1) * 2];
                    unsigned b1 = kb[j >> 1][(j & 1) * 2 + 1];
                    mma_tf32(s[0][j], qa[0][ks], b0, b1);
                    mma_tf32(s[1][j], qa[1][ks], b0, b1);
                }
            }

            // ---- mask + full-tile row max + rescale O ----
            float mn[2][2], al[2][2];
            #pragma unroll
            for (int im = 0; im < 2; im++) {
                const int base   = q0 + w * 32 + im * 16;
                const int row_lo = base + qrl;
                const bool domask = (k0 + 63 > base);
                float tml = -1e30f, tmh = -1e30f;
                #pragma unroll
                for (int j = 0; j < 8; j++) {
                    if (domask) {
                        int col = k0 + j * 8 + 2 * quad;
                        if (col     > row_lo)     s[im][j][0] = -1e30f;
                        if (col + 1 > row_lo)     s[im][j][1] = -1e30f;
                        if (col     > row_lo + 8) s[im][j][2] = -1e30f;
                        if (col + 1 > row_lo + 8) s[im][j][3] = -1e30f;
                    }
                    tml = fmaxf(tml, fmaxf(s[im][j][0], s[im][j][1]));
                    tmh = fmaxf(tmh, fmaxf(s[im][j][2], s[im][j][3]));
                }
                tml = fmaxf(tml, __shfl_xor_sync(0xffffffffu, tml, 1));
                tml = fmaxf(tml, __shfl_xor_sync(0xffffffffu, tml, 2));
                tmh = fmaxf(tmh, __shfl_xor_sync(0xffffffffu, tmh, 1));
                tmh = fmaxf(tmh, __shfl_xor_sync(0xffffffffu, tmh, 2));

                mn[im][0] = fmaxf(mm[im][0], tml);
                mn[im][1] = fmaxf(mm[im][1], tmh);
                al[im][0] = __expf(mm[im][0] - mn[im][0]);
                al[im][1] = __expf(mm[im][1] - mn[im][1]);
                mm[im][0] = mn[im][0]; mm[im][1] = mn[im][1];
                #pragma unroll
                for (int n = 0; n < 8; n++) {
                    o[im][n][0] *= al[im][0]; o[im][n][1] *= al[im][0];
                    o[im][n][2] *= al[im][1]; o[im][n][3] *= al[im][1];
                }
            }

            // ---- two 32-key halves: exp + store P, then PV (all ldmatrix) ----
            float rs[2][2] = {{0.0f, 0.0f}, {0.0f, 0.0f}};
            #pragma unroll
            for (int hf = 0; hf < 2; hf++) {
                #pragma unroll
                for (int im = 0; im < 2; im++) {
                    const int rl = w * 32 + im * 16 + qrl;
                    #pragma unroll
                    for (int jj = 0; jj < 4; jj++) {
                        int j = hf * 4 + jj;
                        float p0 = __expf(s[im][j][0] - mn[im][0]);
                        float p1 = __expf(s[im][j][1] - mn[im][0]);
                        float p2 = __expf(s[im][j][2] - mn[im][1]);
                        float p3 = __expf(s[im][j][3] - mn[im][1]);
                        rs[im][0] += p0 + p1;
                        rs[im][1] += p2 + p3;
                        *(float2*)&Psm[rl * PSTR2 + jj * 8 + 2 * quad] =
                            make_float2(tf32r(p0), tf32r(p1));
                        *(float2*)&Psm[(rl + 8) * PSTR2 + jj * 8 + 2 * quad] =
                            make_float2(tf32r(p2), tf32r(p3));
                    }
                }
                __syncwarp();

                #pragma unroll
                for (int ksl = 0; ksl < 4; ksl++) {
                    // P a-fragments via ldmatrix (same formula as GEMM A)
                    unsigned ap[2][4];
                    #pragma unroll
                    for (int im = 0; im < 2; im++) {
                        int prow = w * 32 + im * 16 + rr + ((mtx & 1) << 3);
                        int kch  = ksl * 2 + (mtx >> 1);
                        uint32_t addr = psb + (uint32_t)prow * (PSTR2 * 4u)
                                      + (uint32_t)(kch << 4);
                        ldsm4(ap[im], addr);
                    }
                    // V^T b-fragments via ldmatrix (same formula as GEMM B)
                    unsigned vb[4][4];
                    #pragma unroll
                    for (int j2 = 0; j2 < 4; j2++) {
                        int vrow = j2 * 16 + rr + ((mtx >> 1) << 3);
                        int kch  = (hf * 4 + ksl) * 2 + (mtx & 1);
                        uint32_t addr = Vtb + (uint32_t)vrow * 256u
                                      + (uint32_t)((kch ^ (vrow & 7)) << 4);
                        ldsm4(vb[j2], addr);
                    }
                    #pragma unroll
                    for (int im = 0; im < 2; im++)
                        #pragma unroll
                        for (int n = 0; n < 8; n++)
                            mma_tf32(o[im][n], ap[im],
                                     vb[n >> 1][(n & 1) * 2],
                                     vb[n >> 1][(n & 1) * 2 + 1]);
                }
                __syncwarp();
            }

            // ---- l update ----
            #pragma unroll
            for (int im = 0; im < 2; im++) {
                float rsl = rs[im][0], rsh = rs[im][1];
                rsl += __shfl_xor_sync(0xffffffffu, rsl, 1);
                rsl += __shfl_xor_sync(0xffffffffu, rsl, 2);
                rsh += __shfl_xor_sync(0xffffffffu, rsh, 1);
                rsh += __shfl_xor_sync(0xffffffffu, rsh, 2);
                ll[im][0] = ll[im][0] * al[im][0] + rsl;
                ll[im][1] = ll[im][1] * al[im][1] + rsh;
            }
        }
    }

    // ---- epilogue: normalize + round (feeds tf32 proj GEMM) ----
    #pragma unroll
    for (int im = 0; im < 2; im++) {
        float invl = 1.0f / ll[im][0];
        float invh = 1.0f / ll[im][1];
        int rl = q0 + w * 32 + im * 16 + qrl;
        #pragma unroll
        for (int n = 0; n < 8; n++) {
            int col = h * HDIM + n * 8 + 2 * quad;
            *(float2*)&g_att[(size_t)rl * CC + col] =
                make_float2(tf32r(o[im][n][0] * invl), tf32r(o[im][n][1] * invl));
            *(float2*)&g_att[(size_t)(rl + 8) * CC + col] =
                make_float2(tf32r(o[im][n][2] * invh), tf32r(o[im][n][3] * invh));
        }
    }
}

// ================================ launch ===================================
extern "C" void kernel_launch(void* const* d_in, const int* in_sizes, int n_in,
                              void* d_out, int out_size)
{
    const float* x      = (const float*)d_in[0];
    const float* W_attn = (const float*)d_in[1];
    const float* b_attn = (const float*)d_in[2];
    const float* W_proj = (const float*)d_in[3];
    const float* b_proj = (const float*)d_in[4];
    float*       out    = (float*)d_out;

    void *qkv_p, *att_p, *xr_p, *wat_p, *wpt_p, *vt_p;
    cudaGetSymbolAddress(&qkv_p, g_qkv);
    cudaGetSymbolAddress(&att_p, g_att);
    cudaGetSymbolAddress(&xr_p,  g_xr);
    cudaGetSymbolAddress(&wat_p, g_wat);
    cudaGetSymbolAddress(&wpt_p, g_wpt);
    cudaGetSymbolAddress(&vt_p,  g_vt);
    float* qkv = (float*)qkv_p;
    float* att = (float*)att_p;
    float* xr  = (float*)xr_p;
    float* wat = (float*)wat_p;
    float* wpt = (float*)wpt_p;
    float* vt  = (float*)vt_p;

    cudaFuncSetAttribute(gemm_tc,
                         cudaFuncAttributeMaxDynamicSharedMemorySize, GEMM_SMEM);
    cudaFuncSetAttribute(flash_attn_tc,
                         cudaFuncAttributeMaxDynamicSharedMemorySize, ATT_SMEM);

    // 0) pre-pass
    {
        int n4 = TT * CC / 4;
        round_copy<<<(n4 + 255) / 256, 256>>>(x, xr, n4);
        transpose_round<<<dim3(3 * CC / 32, CC / 32), dim3(32, 8)>>>(W_attn, wat, CC, 3 * CC);
        transpose_round<<<dim3(CC / 32, CC / 32), dim3(32, 8)>>>(W_proj, wpt, CC, CC);
    }
    // 1) QKV projection (rounded output + V^T side-write)
    {
        dim3 grid(3 * CC / 128, TT / 128);
        gemm_tc<<<grid, 256, GEMM_SMEM>>>(xr, wat, b_attn, qkv, TT, 3 * CC, CC, 1, vt);
    }
    // 2) Causal flash attention (1D grid, global heavy-first)
    {
        flash_attn_tc<<<512, 128, ATT_SMEM>>>();
    }
    // 3) Output projection
    {
        dim3 grid(CC / 128, TT / 128);
        gemm_tc<<<grid, 256, GEMM_SMEM>>>(att, wpt, b_proj, out, TT, CC, CC, 0, nullptr);
    }
}